// round 4
// baseline (speedup 1.0000x reference)
#include <cuda_runtime.h>
#include <stdint.h>

#define N_NODES 100000
#define N_EDGES 1200000
#define HID     64
#define TGT     32
#define NLAY    3
#define NGRAPH  500
#define OUTW    (NLAY*TGT)   // 96
#define SCAN_B  1024
#define NBLK    ((N_NODES + SCAN_B - 1)/SCAN_B)   // 98

typedef unsigned long long ull;

// ---------------------------------------------------------------- scratch
static __device__ float g_feat[N_NODES*HID];
static __device__ float g_h   [N_NODES*HID];
static __device__ float g_gsum [NGRAPH*HID];
static __device__ float g_gvar [NGRAPH*HID];
static __device__ float g_alpha[NGRAPH*HID];
static __device__ float g_beta [NGRAPH*HID];
static __device__ float g_cnt  [NGRAPH];
static __device__ int   g_deg  [N_NODES];
static __device__ int   g_off  [N_NODES+1];
static __device__ int   g_cursor[N_NODES];
static __device__ int   g_csr  [N_EDGES];
static __device__ int   g_bsum [NBLK];

// ---------------------------------------------------------------- f32x2
__device__ __forceinline__ ull pk2(float x, float y) {
    ull r; asm("mov.b64 %0, {%1, %2};" : "=l"(r) : "f"(x), "f"(y)); return r;
}
__device__ __forceinline__ float2 up2(ull v) {
    float lo, hi; asm("mov.b64 {%0, %1}, %2;" : "=f"(lo), "=f"(hi) : "l"(v));
    return make_float2(lo, hi);
}
__device__ __forceinline__ ull ffma2(ull a, ull b, ull c) {
    ull d; asm("fma.rn.f32x2 %0, %1, %2, %3;" : "=l"(d) : "l"(a), "l"(b), "l"(c));
    return d;
}

// ---------------------------------------------------------------- setup

__global__ void k_zero_once(float* __restrict__ out) {
    int i = blockIdx.x*blockDim.x + threadIdx.x;
    if (i < N_NODES) g_deg[i] = 0;
    if (i < NGRAPH)  g_cnt[i] = 0.f;
    if (i < NGRAPH*HID) { g_gsum[i] = 0.f; g_gvar[i] = 0.f; }
    if (i < NGRAPH*OUTW) out[i] = 0.f;
}

__global__ void k_hist(const int* __restrict__ dst) {
    int e = blockIdx.x*blockDim.x + threadIdx.x;
    if (e < N_EDGES) atomicAdd(&g_deg[dst[e]], 1);
}

__global__ void k_count(const int* __restrict__ gid) {
    int i = blockIdx.x*blockDim.x + threadIdx.x;
    if (i < N_NODES) atomicAdd(&g_cnt[gid[i]], 1.0f);
}

// ---------------- two-level exclusive scan of degrees

__global__ __launch_bounds__(SCAN_B) void k_scan1() {
    __shared__ int wsum[32];
    int i = blockIdx.x*SCAN_B + threadIdx.x;
    int lane = threadIdx.x & 31, wid = threadIdx.x >> 5;
    int v = (i < N_NODES) ? g_deg[i] : 0;
    int s = v;
    #pragma unroll
    for (int o = 1; o < 32; o <<= 1) {
        int t = __shfl_up_sync(~0u, s, o);
        if (lane >= o) s += t;
    }
    if (lane == 31) wsum[wid] = s;
    __syncthreads();
    if (wid == 0) {
        int ws = wsum[lane];
        #pragma unroll
        for (int o = 1; o < 32; o <<= 1) {
            int t = __shfl_up_sync(~0u, ws, o);
            if (lane >= o) ws += t;
        }
        wsum[lane] = ws;
    }
    __syncthreads();
    int excl = s - v + ((wid > 0) ? wsum[wid-1] : 0);
    if (i < N_NODES) g_off[i] = excl;
    if (threadIdx.x == SCAN_B-1) g_bsum[blockIdx.x] = wsum[31];
}

__global__ __launch_bounds__(128) void k_scan2() {
    __shared__ int buf[128];
    int tid = threadIdx.x;
    int v = (tid < NBLK) ? g_bsum[tid] : 0;
    buf[tid] = v;
    __syncthreads();
    #pragma unroll
    for (int o = 1; o < 128; o <<= 1) {
        int t = (tid >= o) ? buf[tid - o] : 0;
        __syncthreads();
        buf[tid] += t;
        __syncthreads();
    }
    if (tid < NBLK) g_bsum[tid] = buf[tid] - v;
    if (tid == 127) g_off[N_NODES] = buf[127];
}

__global__ void k_scan3() {
    int i = blockIdx.x*blockDim.x + threadIdx.x;
    if (i < N_NODES) {
        int o = g_off[i] + g_bsum[i >> 10];
        g_off[i] = o;
        g_cursor[i] = o;
    }
}

__global__ void k_scatter(const int* __restrict__ src, const int* __restrict__ dst) {
    int e = blockIdx.x*blockDim.x + threadIdx.x;
    if (e < N_EDGES) {
        int p = atomicAdd(&g_cursor[dst[e]], 1);
        g_csr[p] = src[e];
    }
}

// ============================================================ fused kernel 1
// gather (GIN agg) -> MLP(2 GEMMs, even/odd-k packed FFMA2) -> h + GN stats
__global__ __launch_bounds__(256) void k_conv(
    const float* __restrict__ w1, const float* __restrict__ b1,
    const float* __restrict__ w2, const float* __restrict__ b2,
    const int*   __restrict__ gid,
    const float* __restrict__ x, int use_x,
    const float* __restrict__ eps, int l)
{
    __shared__ float W1t[64*68];     // W1t[c*68+k] = w1[k*64+c]
    __shared__ float W2t[64*68];
    __shared__ float As [64*68];     // As[r*68+k]
    __shared__ float b1s[64], b2s[64];
    __shared__ int   gids[64];

    const int tid  = threadIdx.x;
    const int row0 = blockIdx.x * 64;

    for (int i = tid; i < 4096; i += 256) {
        int k = i >> 6, c = i & 63;
        W1t[c*68 + k] = w1[i];
        W2t[c*68 + k] = w2[i];
    }
    if (tid < 64) {
        b1s[tid] = b1[tid]; b2s[tid] = b2[tid];
        int r = row0 + tid;
        gids[tid] = (r < N_NODES) ? gid[r] : 0;
    }

    // ---- gather: 4 lanes per node, 16 cols per lane, register accumulate
    {
        const float* __restrict__ f = use_x ? x : g_feat;
        const float  sc = 1.0f + eps[l];
        const int r     = tid >> 2;
        const int row   = row0 + r;
        const int jb    = (tid & 3) << 4;
        float4 A0 = make_float4(0.f,0.f,0.f,0.f), A1 = A0, A2 = A0, A3 = A0;
        if (row < N_NODES) {
            const float* fr = f + (size_t)row*64 + jb;
            A0 = *(const float4*)(fr+0);  A1 = *(const float4*)(fr+4);
            A2 = *(const float4*)(fr+8);  A3 = *(const float4*)(fr+12);
            A0.x*=sc; A0.y*=sc; A0.z*=sc; A0.w*=sc;
            A1.x*=sc; A1.y*=sc; A1.z*=sc; A1.w*=sc;
            A2.x*=sc; A2.y*=sc; A2.z*=sc; A2.w*=sc;
            A3.x*=sc; A3.y*=sc; A3.z*=sc; A3.w*=sc;
            int b = g_off[row], e = g_off[row+1];
            for (; b + 2 <= e; b += 2) {
                const float* p0 = f + (size_t)g_csr[b]  *64 + jb;
                const float* p1 = f + (size_t)g_csr[b+1]*64 + jb;
                float4 u0 = *(const float4*)(p0+0), v0 = *(const float4*)(p1+0);
                float4 u1 = *(const float4*)(p0+4), v1 = *(const float4*)(p1+4);
                float4 u2 = *(const float4*)(p0+8), v2 = *(const float4*)(p1+8);
                float4 u3 = *(const float4*)(p0+12),v3 = *(const float4*)(p1+12);
                A0.x += u0.x+v0.x; A0.y += u0.y+v0.y; A0.z += u0.z+v0.z; A0.w += u0.w+v0.w;
                A1.x += u1.x+v1.x; A1.y += u1.y+v1.y; A1.z += u1.z+v1.z; A1.w += u1.w+v1.w;
                A2.x += u2.x+v2.x; A2.y += u2.y+v2.y; A2.z += u2.z+v2.z; A2.w += u2.w+v2.w;
                A3.x += u3.x+v3.x; A3.y += u3.y+v3.y; A3.z += u3.z+v3.z; A3.w += u3.w+v3.w;
            }
            if (b < e) {
                const float* p0 = f + (size_t)g_csr[b]*64 + jb;
                float4 u0 = *(const float4*)(p0+0);
                float4 u1 = *(const float4*)(p0+4);
                float4 u2 = *(const float4*)(p0+8);
                float4 u3 = *(const float4*)(p0+12);
                A0.x += u0.x; A0.y += u0.y; A0.z += u0.z; A0.w += u0.w;
                A1.x += u1.x; A1.y += u1.y; A1.z += u1.z; A1.w += u1.w;
                A2.x += u2.x; A2.y += u2.y; A2.z += u2.z; A2.w += u2.w;
                A3.x += u3.x; A3.y += u3.y; A3.z += u3.z; A3.w += u3.w;
            }
        }
        float* as = &As[r*68 + jb];
        *(float4*)(as+0) = A0; *(float4*)(as+4) = A1;
        *(float4*)(as+8) = A2; *(float4*)(as+12) = A3;
    }
    __syncthreads();

    const int c  = tid & 63;           // output column
    const int rg = tid >> 6;           // row group: rows rg*16 .. rg*16+15
    const float* arow = &As[rg*16*68];

    // ---- GEMM1: even/odd-k split accumulation
    ull acc[16];
    {
        ull binit = pk2(b1s[c], 0.f);
        #pragma unroll
        for (int rr = 0; rr < 16; rr++) acc[rr] = binit;
    }
    const float* wc1 = &W1t[c*68];
    #pragma unroll 4
    for (int kc = 0; kc < 64; kc += 4) {
        float4 w = *(const float4*)&wc1[kc];
        ull wp0 = pk2(w.x, w.y), wp1 = pk2(w.z, w.w);
        #pragma unroll
        for (int rr = 0; rr < 16; rr++) {
            float4 a = *(const float4*)&arow[rr*68 + kc];
            acc[rr] = ffma2(pk2(a.x, a.y), wp0, acc[rr]);
            acc[rr] = ffma2(pk2(a.z, a.w), wp1, acc[rr]);
        }
    }
    __syncthreads();
    #pragma unroll
    for (int rr = 0; rr < 16; rr++) {
        float2 p = up2(acc[rr]);
        As[(rg*16+rr)*68 + c] = fmaxf(p.x + p.y, 0.f);
    }
    __syncthreads();

    // ---- GEMM2
    {
        ull binit = pk2(b2s[c], 0.f);
        #pragma unroll
        for (int rr = 0; rr < 16; rr++) acc[rr] = binit;
    }
    const float* wc2 = &W2t[c*68];
    #pragma unroll 4
    for (int kc = 0; kc < 64; kc += 4) {
        float4 w = *(const float4*)&wc2[kc];
        ull wp0 = pk2(w.x, w.y), wp1 = pk2(w.z, w.w);
        #pragma unroll
        for (int rr = 0; rr < 16; rr++) {
            float4 a = *(const float4*)&arow[rr*68 + kc];
            acc[rr] = ffma2(pk2(a.x, a.y), wp0, acc[rr]);
            acc[rr] = ffma2(pk2(a.z, a.w), wp1, acc[rr]);
        }
    }

    // ---- epilogue: write h, per-graph sum(h), sum(h^2)
    float s = 0.f, q = 0.f;
    int cur = gids[rg*16];
    #pragma unroll
    for (int rr = 0; rr < 16; rr++) {
        int row = row0 + rg*16 + rr;
        if (row < N_NODES) {
            float2 p = up2(acc[rr]);
            float h = p.x + p.y;
            g_h[(size_t)row*64 + c] = h;
            int g = gids[rg*16 + rr];
            if (g != cur) {
                atomicAdd(&g_gsum[cur*64 + c], s);
                atomicAdd(&g_gvar[cur*64 + c], q);
                s = 0.f; q = 0.f; cur = g;
            }
            s += h; q += h*h;
        }
    }
    atomicAdd(&g_gsum[cur*64 + c], s);
    atomicAdd(&g_gvar[cur*64 + c], q);
}

// ------------------------------------------------ per-(graph,ch) norm coeffs
__global__ void k_stats(const float* __restrict__ gns,
                        const float* __restrict__ gnw,
                        const float* __restrict__ gnb) {
    int i = blockIdx.x*blockDim.x + threadIdx.x;
    if (i >= NGRAPH*HID) return;
    int c = i & 63, g = i >> 6;
    float n  = fmaxf(g_cnt[g], 1.f);
    float m  = g_gsum[i] / n;
    float e2 = g_gvar[i] / n;
    float s  = gns[c];
    float var = e2 - m*m*s*(2.f - s);
    float sd  = sqrtf(fmaxf(var, 0.f) + 1e-8f);
    float al  = gnw[c] / sd;
    g_alpha[i] = al;
    g_beta[i]  = gnb[c] - al*m*s;
    g_gsum[i] = 0.f;
    g_gvar[i] = 0.f;
}

// ============================================================ fused kernel 2
// GraphNorm affine+relu -> proj MLP (2 GEMMs) -> per-graph pooled out
__global__ __launch_bounds__(256) void k_proj(
    const float* __restrict__ pw1, const float* __restrict__ pb1,
    const float* __restrict__ pw2, const float* __restrict__ pb2,
    const int*   __restrict__ gid, float* __restrict__ out, int l)
{
    __shared__ float W1t[64*68];     // 64 cols
    __shared__ float W2t[32*68];     // 32 cols
    __shared__ float As [64*68];
    __shared__ float b1s[64], b2s[32];
    __shared__ int   gids[64];

    const int tid  = threadIdx.x;
    const int row0 = blockIdx.x * 64;

    for (int i = tid; i < 4096; i += 256) {
        int k = i >> 6, c = i & 63;
        W1t[c*68 + k] = pw1[i];
    }
    for (int i = tid; i < 2048; i += 256) {
        int k = i >> 5, c = i & 31;
        W2t[c*68 + k] = pw2[i];
    }
    if (tid < 64) {
        b1s[tid] = pb1[tid];
        int r = row0 + tid;
        gids[tid] = (r < N_NODES) ? gid[r] : 0;
    }
    if (tid < 32) b2s[tid] = pb2[tid];
    __syncthreads();

    // ---- GraphNorm affine + relu -> As (+ g_feat for next layer)
    #pragma unroll
    for (int it = 0; it < 4; it++) {
        int i = it*256 + tid;
        int r = i >> 4, kk = (i & 15) << 2;
        int row = row0 + r;
        float4 v = make_float4(0.f,0.f,0.f,0.f);
        if (row < N_NODES) {
            int g = gids[r];
            float4 h  = *(const float4*)&g_h[(size_t)row*64 + kk];
            float4 al = *(const float4*)&g_alpha[g*64 + kk];
            float4 be = *(const float4*)&g_beta[g*64 + kk];
            v.x = fmaxf(fmaf(al.x, h.x, be.x), 0.f);
            v.y = fmaxf(fmaf(al.y, h.y, be.y), 0.f);
            v.z = fmaxf(fmaf(al.z, h.z, be.z), 0.f);
            v.w = fmaxf(fmaf(al.w, h.w, be.w), 0.f);
            *(float4*)&g_feat[(size_t)row*64 + kk] = v;
        }
        *(float4*)&As[r*68 + kk] = v;
    }
    __syncthreads();

    // ---- GEMM1: 64x64
    {
        const int c  = tid & 63;
        const int rg = tid >> 6;
        const float* arow = &As[rg*16*68];
        ull acc[16];
        ull binit = pk2(b1s[c], 0.f);
        #pragma unroll
        for (int rr = 0; rr < 16; rr++) acc[rr] = binit;
        const float* wc1 = &W1t[c*68];
        #pragma unroll 4
        for (int kc = 0; kc < 64; kc += 4) {
            float4 w = *(const float4*)&wc1[kc];
            ull wp0 = pk2(w.x, w.y), wp1 = pk2(w.z, w.w);
            #pragma unroll
            for (int rr = 0; rr < 16; rr++) {
                float4 a = *(const float4*)&arow[rr*68 + kc];
                acc[rr] = ffma2(pk2(a.x, a.y), wp0, acc[rr]);
                acc[rr] = ffma2(pk2(a.z, a.w), wp1, acc[rr]);
            }
        }
        __syncthreads();
        #pragma unroll
        for (int rr = 0; rr < 16; rr++) {
            float2 p = up2(acc[rr]);
            As[(rg*16+rr)*68 + c] = fmaxf(p.x + p.y, 0.f);
        }
    }
    __syncthreads();

    // ---- GEMM2: 64 -> 32, 32 cols x 8 row-groups of 8 rows
    {
        const int c  = tid & 31;
        const int rg = tid >> 5;
        const float* arow = &As[rg*8*68];
        ull acc[8];
        ull binit = pk2(b2s[c], 0.f);
        #pragma unroll
        for (int rr = 0; rr < 8; rr++) acc[rr] = binit;
        const float* wc2 = &W2t[c*68];
        #pragma unroll 4
        for (int kc = 0; kc < 64; kc += 4) {
            float4 w = *(const float4*)&wc2[kc];
            ull wp0 = pk2(w.x, w.y), wp1 = pk2(w.z, w.w);
            #pragma unroll
            for (int rr = 0; rr < 8; rr++) {
                float4 a = *(const float4*)&arow[rr*68 + kc];
                acc[rr] = ffma2(pk2(a.x, a.y), wp0, acc[rr]);
                acc[rr] = ffma2(pk2(a.z, a.w), wp1, acc[rr]);
            }
        }

        // pooling epilogue
        float s = 0.f;
        int cur = gids[rg*8];
        #pragma unroll
        for (int rr = 0; rr < 8; rr++) {
            int row = row0 + rg*8 + rr;
            if (row < N_NODES) {
                float2 p = up2(acc[rr]);
                float z = p.x + p.y;
                int g = gids[rg*8 + rr];
                if (g != cur) {
                    atomicAdd(&out[cur*OUTW + l*TGT + c], s);
                    s = 0.f; cur = g;
                }
                s += z;
            }
        }
        atomicAdd(&out[cur*OUTW + l*TGT + c], s);
    }
}

__global__ void k_final(float* __restrict__ out) {
    int i = blockIdx.x*blockDim.x + threadIdx.x;
    if (i < NGRAPH*OUTW) out[i] /= fmaxf(g_cnt[i / OUTW], 1.f);
}

// ---------------------------------------------------------------- launcher

extern "C" void kernel_launch(void* const* d_in, const int* in_sizes, int n_in,
                              void* d_out, int out_size) {
    const float* x   = (const float*)d_in[0];
    const int*   src = (const int*)  d_in[1];
    const int*   dst = (const int*)  d_in[2];
    const int*   gid = (const int*)  d_in[3];
    const float* eps = (const float*)d_in[4];
    const float* cw1 = (const float*)d_in[5];
    const float* cb1 = (const float*)d_in[6];
    const float* cw2 = (const float*)d_in[7];
    const float* cb2 = (const float*)d_in[8];
    const float* gnw = (const float*)d_in[9];
    const float* gnb = (const float*)d_in[10];
    const float* gns = (const float*)d_in[11];
    const float* pw1 = (const float*)d_in[12];
    const float* pb1 = (const float*)d_in[13];
    const float* pw2 = (const float*)d_in[14];
    const float* pb2 = (const float*)d_in[15];
    float* out = (float*)d_out;

    const int EB = (N_EDGES + 255)/256;
    const int NB = (N_NODES + 255)/256;

    k_zero_once<<<NB, 256>>>(out);
    k_hist<<<EB, 256>>>(dst);
    k_count<<<NB, 256>>>(gid);
    k_scan1<<<NBLK, SCAN_B>>>();
    k_scan2<<<1, 128>>>();
    k_scan3<<<NB, 256>>>();
    k_scatter<<<EB, 256>>>(src, dst);

    const int GB = (N_NODES + 63)/64;

    for (int l = 0; l < NLAY; l++) {
        int use_x = (l == 0) ? 1 : 0;
        k_conv<<<GB, 256>>>(cw1 + l*4096, cb1 + l*64,
                            cw2 + l*4096, cb2 + l*64, gid,
                            x, use_x, eps, l);
        k_stats<<<(NGRAPH*HID + 255)/256, 256>>>(gns + l*64, gnw + l*64, gnb + l*64);
        k_proj<<<GB, 256>>>(pw1 + l*4096, pb1 + l*64,
                            pw2 + l*2048, pb2 + l*32,
                            gid, out, l);
    }
    k_final<<<(NGRAPH*OUTW + 255)/256, 256>>>(out);
}

// round 5
// speedup vs baseline: 1.1221x; 1.1221x over previous
#include <cuda_runtime.h>
#include <stdint.h>

#define N_NODES 100000
#define N_EDGES 1200000
#define HID     64
#define TGT     32
#define NLAY    3
#define NGRAPH  500
#define OUTW    (NLAY*TGT)   // 96
#define SCAN_B  1024
#define NBLK    ((N_NODES + SCAN_B - 1)/SCAN_B)   // 98

typedef unsigned long long ull;

// ---------------------------------------------------------------- scratch
static __device__ float g_feat[N_NODES*HID];
static __device__ float g_A   [N_NODES*HID];
static __device__ float g_h   [N_NODES*HID];
static __device__ float g_gsum [NGRAPH*HID];
static __device__ float g_gvar [NGRAPH*HID];
static __device__ float g_alpha[NGRAPH*HID];
static __device__ float g_beta [NGRAPH*HID];
static __device__ float g_cnt  [NGRAPH];
static __device__ int   g_deg  [N_NODES];
static __device__ int   g_off  [N_NODES+1];
static __device__ int   g_cursor[N_NODES];
static __device__ int   g_csr  [N_EDGES];
static __device__ int   g_bsum [NBLK];

// ---------------------------------------------------------------- f32x2
__device__ __forceinline__ ull pk2(float x, float y) {
    ull r; asm("mov.b64 %0, {%1, %2};" : "=l"(r) : "f"(x), "f"(y)); return r;
}
__device__ __forceinline__ float2 up2(ull v) {
    float lo, hi; asm("mov.b64 {%0, %1}, %2;" : "=f"(lo), "=f"(hi) : "l"(v));
    return make_float2(lo, hi);
}
__device__ __forceinline__ ull ffma2(ull a, ull b, ull c) {
    ull d; asm("fma.rn.f32x2 %0, %1, %2, %3;" : "=l"(d) : "l"(a), "l"(b), "l"(c));
    return d;
}

// ---------------------------------------------------------------- setup

__global__ void k_zero_once(float* __restrict__ out) {
    int i = blockIdx.x*blockDim.x + threadIdx.x;
    if (i < N_NODES) g_deg[i] = 0;
    if (i < NGRAPH)  g_cnt[i] = 0.f;
    if (i < NGRAPH*HID) { g_gsum[i] = 0.f; g_gvar[i] = 0.f; }
    if (i < NGRAPH*OUTW) out[i] = 0.f;
}

__global__ void k_hist(const int* __restrict__ dst) {
    int e = blockIdx.x*blockDim.x + threadIdx.x;
    if (e < N_EDGES) atomicAdd(&g_deg[dst[e]], 1);
}

__global__ void k_count(const int* __restrict__ gid) {
    int i = blockIdx.x*blockDim.x + threadIdx.x;
    if (i < N_NODES) atomicAdd(&g_cnt[gid[i]], 1.0f);
}

// ---------------- two-level exclusive scan of degrees

__global__ __launch_bounds__(SCAN_B) void k_scan1() {
    __shared__ int wsum[32];
    int i = blockIdx.x*SCAN_B + threadIdx.x;
    int lane = threadIdx.x & 31, wid = threadIdx.x >> 5;
    int v = (i < N_NODES) ? g_deg[i] : 0;
    int s = v;
    #pragma unroll
    for (int o = 1; o < 32; o <<= 1) {
        int t = __shfl_up_sync(~0u, s, o);
        if (lane >= o) s += t;
    }
    if (lane == 31) wsum[wid] = s;
    __syncthreads();
    if (wid == 0) {
        int ws = wsum[lane];
        #pragma unroll
        for (int o = 1; o < 32; o <<= 1) {
            int t = __shfl_up_sync(~0u, ws, o);
            if (lane >= o) ws += t;
        }
        wsum[lane] = ws;
    }
    __syncthreads();
    int excl = s - v + ((wid > 0) ? wsum[wid-1] : 0);
    if (i < N_NODES) g_off[i] = excl;
    if (threadIdx.x == SCAN_B-1) g_bsum[blockIdx.x] = wsum[31];
}

__global__ __launch_bounds__(128) void k_scan2() {
    __shared__ int buf[128];
    int tid = threadIdx.x;
    int v = (tid < NBLK) ? g_bsum[tid] : 0;
    buf[tid] = v;
    __syncthreads();
    #pragma unroll
    for (int o = 1; o < 128; o <<= 1) {
        int t = (tid >= o) ? buf[tid - o] : 0;
        __syncthreads();
        buf[tid] += t;
        __syncthreads();
    }
    if (tid < NBLK) g_bsum[tid] = buf[tid] - v;
    if (tid == 127) g_off[N_NODES] = buf[127];
}

__global__ void k_scan3() {
    int i = blockIdx.x*blockDim.x + threadIdx.x;
    if (i < N_NODES) {
        int o = g_off[i] + g_bsum[i >> 10];
        g_off[i] = o;
        g_cursor[i] = o;
    }
}

__global__ void k_scatter(const int* __restrict__ src, const int* __restrict__ dst) {
    int e = blockIdx.x*blockDim.x + threadIdx.x;
    if (e < N_EDGES) {
        int p = atomicAdd(&g_cursor[dst[e]], 1);
        g_csr[p] = src[e];
    }
}

// ------------------------------------------------ aggregation (CSR gather)
// 16 lanes per node, each lane owns 4 columns. A = (1+eps)*feat + sum(neigh)
__global__ __launch_bounds__(256) void k_agg(const float* __restrict__ x, int use_x,
                                             const float* __restrict__ eps, int l) {
    unsigned t = blockIdx.x*blockDim.x + threadIdx.x;
    unsigned node = t >> 4;
    if (node >= N_NODES) return;
    int j = (int)(t & 15u) << 2;
    const float* __restrict__ f = use_x ? x : g_feat;
    float sc = 1.0f + eps[l];
    float4 acc = *(const float4*)&f[(size_t)node*HID + j];
    acc.x *= sc; acc.y *= sc; acc.z *= sc; acc.w *= sc;
    int b = g_off[node], e = g_off[node+1];
    for (; b + 4 <= e; b += 4) {
        int s0 = g_csr[b], s1 = g_csr[b+1], s2 = g_csr[b+2], s3 = g_csr[b+3];
        float4 v0 = *(const float4*)&f[(size_t)s0*HID + j];
        float4 v1 = *(const float4*)&f[(size_t)s1*HID + j];
        float4 v2 = *(const float4*)&f[(size_t)s2*HID + j];
        float4 v3 = *(const float4*)&f[(size_t)s3*HID + j];
        acc.x += (v0.x + v1.x) + (v2.x + v3.x);
        acc.y += (v0.y + v1.y) + (v2.y + v3.y);
        acc.z += (v0.z + v1.z) + (v2.z + v3.z);
        acc.w += (v0.w + v1.w) + (v2.w + v3.w);
    }
    for (; b < e; b++) {
        int s = g_csr[b];
        float4 v = *(const float4*)&f[(size_t)s*HID + j];
        acc.x += v.x; acc.y += v.y; acc.z += v.z; acc.w += v.w;
    }
    *(float4*)&g_A[(size_t)node*HID + j] = acc;
}

// ============================================================ fused kernel 1
// MLP (2 GEMMs, even/odd-k packed FFMA2, transposed weights) + GN stats
__global__ __launch_bounds__(256) void k_conv(
    const float* __restrict__ w1, const float* __restrict__ b1,
    const float* __restrict__ w2, const float* __restrict__ b2,
    const int*   __restrict__ gid)
{
    __shared__ float W1t[64*68];     // W1t[c*68+k] = w1[k*64+c]
    __shared__ float W2t[64*68];
    __shared__ float As [64*68];     // As[r*68+k]
    __shared__ float b1s[64], b2s[64];
    __shared__ int   gids[64];

    const int tid  = threadIdx.x;
    const int row0 = blockIdx.x * 64;

    for (int i = tid; i < 4096; i += 256) {
        int k = i >> 6, c = i & 63;
        W1t[c*68 + k] = w1[i];
        W2t[c*68 + k] = w2[i];
    }
    if (tid < 64) {
        b1s[tid] = b1[tid]; b2s[tid] = b2[tid];
        int r = row0 + tid;
        gids[tid] = (r < N_NODES) ? gid[r] : 0;
    }
    #pragma unroll
    for (int it = 0; it < 4; it++) {
        int i = it*256 + tid;
        int r = i >> 4, kk = (i & 15) << 2;
        int row = row0 + r;
        float4 v = make_float4(0.f,0.f,0.f,0.f);
        if (row < N_NODES) v = *(const float4*)&g_A[(size_t)row*64 + kk];
        *(float4*)&As[r*68 + kk] = v;
    }
    __syncthreads();

    const int c  = tid & 63;           // output column
    const int rg = tid >> 6;           // row group: rows rg*16 .. rg*16+15
    const float* arow = &As[rg*16*68];

    // ---- GEMM1: even/odd-k split accumulation
    ull acc[16];
    {
        ull binit = pk2(b1s[c], 0.f);
        #pragma unroll
        for (int rr = 0; rr < 16; rr++) acc[rr] = binit;
    }
    const float* wc1 = &W1t[c*68];
    #pragma unroll 4
    for (int kc = 0; kc < 64; kc += 4) {
        float4 w = *(const float4*)&wc1[kc];
        ull wp0 = pk2(w.x, w.y), wp1 = pk2(w.z, w.w);
        #pragma unroll
        for (int rr = 0; rr < 16; rr++) {
            float4 a = *(const float4*)&arow[rr*68 + kc];
            acc[rr] = ffma2(pk2(a.x, a.y), wp0, acc[rr]);
            acc[rr] = ffma2(pk2(a.z, a.w), wp1, acc[rr]);
        }
    }
    __syncthreads();
    #pragma unroll
    for (int rr = 0; rr < 16; rr++) {
        float2 p = up2(acc[rr]);
        As[(rg*16+rr)*68 + c] = fmaxf(p.x + p.y, 0.f);
    }
    __syncthreads();

    // ---- GEMM2
    {
        ull binit = pk2(b2s[c], 0.f);
        #pragma unroll
        for (int rr = 0; rr < 16; rr++) acc[rr] = binit;
    }
    const float* wc2 = &W2t[c*68];
    #pragma unroll 4
    for (int kc = 0; kc < 64; kc += 4) {
        float4 w = *(const float4*)&wc2[kc];
        ull wp0 = pk2(w.x, w.y), wp1 = pk2(w.z, w.w);
        #pragma unroll
        for (int rr = 0; rr < 16; rr++) {
            float4 a = *(const float4*)&arow[rr*68 + kc];
            acc[rr] = ffma2(pk2(a.x, a.y), wp0, acc[rr]);
            acc[rr] = ffma2(pk2(a.z, a.w), wp1, acc[rr]);
        }
    }

    // ---- epilogue: write h, per-graph sum(h), sum(h^2)
    float s = 0.f, q = 0.f;
    int cur = gids[rg*16];
    #pragma unroll
    for (int rr = 0; rr < 16; rr++) {
        int row = row0 + rg*16 + rr;
        if (row < N_NODES) {
            float2 p = up2(acc[rr]);
            float h = p.x + p.y;
            g_h[(size_t)row*64 + c] = h;
            int g = gids[rg*16 + rr];
            if (g != cur) {
                atomicAdd(&g_gsum[cur*64 + c], s);
                atomicAdd(&g_gvar[cur*64 + c], q);
                s = 0.f; q = 0.f; cur = g;
            }
            s += h; q += h*h;
        }
    }
    atomicAdd(&g_gsum[cur*64 + c], s);
    atomicAdd(&g_gvar[cur*64 + c], q);
}

// ------------------------------------------------ per-(graph,ch) norm coeffs
__global__ void k_stats(const float* __restrict__ gns,
                        const float* __restrict__ gnw,
                        const float* __restrict__ gnb) {
    int i = blockIdx.x*blockDim.x + threadIdx.x;
    if (i >= NGRAPH*HID) return;
    int c = i & 63, g = i >> 6;
    float n  = fmaxf(g_cnt[g], 1.f);
    float m  = g_gsum[i] / n;
    float e2 = g_gvar[i] / n;
    float s  = gns[c];
    float var = e2 - m*m*s*(2.f - s);
    float sd  = sqrtf(fmaxf(var, 0.f) + 1e-8f);
    float al  = gnw[c] / sd;
    g_alpha[i] = al;
    g_beta[i]  = gnb[c] - al*m*s;
    g_gsum[i] = 0.f;
    g_gvar[i] = 0.f;
}

// ============================================================ fused kernel 2
// GraphNorm affine+relu -> proj MLP (2 GEMMs) -> per-graph pooled out
__global__ __launch_bounds__(256) void k_proj(
    const float* __restrict__ pw1, const float* __restrict__ pb1,
    const float* __restrict__ pw2, const float* __restrict__ pb2,
    const int*   __restrict__ gid, float* __restrict__ out, int l)
{
    __shared__ float W1t[64*68];     // 64 cols
    __shared__ float W2t[32*68];     // 32 cols
    __shared__ float As [64*68];
    __shared__ float b1s[64], b2s[32];
    __shared__ int   gids[64];

    const int tid  = threadIdx.x;
    const int row0 = blockIdx.x * 64;

    for (int i = tid; i < 4096; i += 256) {
        int k = i >> 6, c = i & 63;
        W1t[c*68 + k] = pw1[i];
    }
    for (int i = tid; i < 2048; i += 256) {
        int k = i >> 5, c = i & 31;
        W2t[c*68 + k] = pw2[i];
    }
    if (tid < 64) {
        b1s[tid] = pb1[tid];
        int r = row0 + tid;
        gids[tid] = (r < N_NODES) ? gid[r] : 0;
    }
    if (tid < 32) b2s[tid] = pb2[tid];
    __syncthreads();

    // ---- GraphNorm affine + relu -> As (+ g_feat for next layer)
    #pragma unroll
    for (int it = 0; it < 4; it++) {
        int i = it*256 + tid;
        int r = i >> 4, kk = (i & 15) << 2;
        int row = row0 + r;
        float4 v = make_float4(0.f,0.f,0.f,0.f);
        if (row < N_NODES) {
            int g = gids[r];
            float4 h  = *(const float4*)&g_h[(size_t)row*64 + kk];
            float4 al = *(const float4*)&g_alpha[g*64 + kk];
            float4 be = *(const float4*)&g_beta[g*64 + kk];
            v.x = fmaxf(fmaf(al.x, h.x, be.x), 0.f);
            v.y = fmaxf(fmaf(al.y, h.y, be.y), 0.f);
            v.z = fmaxf(fmaf(al.z, h.z, be.z), 0.f);
            v.w = fmaxf(fmaf(al.w, h.w, be.w), 0.f);
            *(float4*)&g_feat[(size_t)row*64 + kk] = v;
        }
        *(float4*)&As[r*68 + kk] = v;
    }
    __syncthreads();

    // ---- GEMM1: 64x64
    {
        const int c  = tid & 63;
        const int rg = tid >> 6;
        const float* arow = &As[rg*16*68];
        ull acc[16];
        ull binit = pk2(b1s[c], 0.f);
        #pragma unroll
        for (int rr = 0; rr < 16; rr++) acc[rr] = binit;
        const float* wc1 = &W1t[c*68];
        #pragma unroll 4
        for (int kc = 0; kc < 64; kc += 4) {
            float4 w = *(const float4*)&wc1[kc];
            ull wp0 = pk2(w.x, w.y), wp1 = pk2(w.z, w.w);
            #pragma unroll
            for (int rr = 0; rr < 16; rr++) {
                float4 a = *(const float4*)&arow[rr*68 + kc];
                acc[rr] = ffma2(pk2(a.x, a.y), wp0, acc[rr]);
                acc[rr] = ffma2(pk2(a.z, a.w), wp1, acc[rr]);
            }
        }
        __syncthreads();
        #pragma unroll
        for (int rr = 0; rr < 16; rr++) {
            float2 p = up2(acc[rr]);
            As[(rg*16+rr)*68 + c] = fmaxf(p.x + p.y, 0.f);
        }
    }
    __syncthreads();

    // ---- GEMM2: 64 -> 32, 32 cols x 8 row-groups of 8 rows
    {
        const int c  = tid & 31;
        const int rg = tid >> 5;
        const float* arow = &As[rg*8*68];
        ull acc[8];
        ull binit = pk2(b2s[c], 0.f);
        #pragma unroll
        for (int rr = 0; rr < 8; rr++) acc[rr] = binit;
        const float* wc2 = &W2t[c*68];
        #pragma unroll 4
        for (int kc = 0; kc < 64; kc += 4) {
            float4 w = *(const float4*)&wc2[kc];
            ull wp0 = pk2(w.x, w.y), wp1 = pk2(w.z, w.w);
            #pragma unroll
            for (int rr = 0; rr < 8; rr++) {
                float4 a = *(const float4*)&arow[rr*68 + kc];
                acc[rr] = ffma2(pk2(a.x, a.y), wp0, acc[rr]);
                acc[rr] = ffma2(pk2(a.z, a.w), wp1, acc[rr]);
            }
        }

        // pooling epilogue
        float s = 0.f;
        int cur = gids[rg*8];
        #pragma unroll
        for (int rr = 0; rr < 8; rr++) {
            int row = row0 + rg*8 + rr;
            if (row < N_NODES) {
                float2 p = up2(acc[rr]);
                float z = p.x + p.y;
                int g = gids[rg*8 + rr];
                if (g != cur) {
                    atomicAdd(&out[cur*OUTW + l*TGT + c], s);
                    s = 0.f; cur = g;
                }
                s += z;
            }
        }
        atomicAdd(&out[cur*OUTW + l*TGT + c], s);
    }
}

__global__ void k_final(float* __restrict__ out) {
    int i = blockIdx.x*blockDim.x + threadIdx.x;
    if (i < NGRAPH*OUTW) out[i] /= fmaxf(g_cnt[i / OUTW], 1.f);
}

// ---------------------------------------------------------------- launcher

extern "C" void kernel_launch(void* const* d_in, const int* in_sizes, int n_in,
                              void* d_out, int out_size) {
    const float* x   = (const float*)d_in[0];
    const int*   src = (const int*)  d_in[1];
    const int*   dst = (const int*)  d_in[2];
    const int*   gid = (const int*)  d_in[3];
    const float* eps = (const float*)d_in[4];
    const float* cw1 = (const float*)d_in[5];
    const float* cb1 = (const float*)d_in[6];
    const float* cw2 = (const float*)d_in[7];
    const float* cb2 = (const float*)d_in[8];
    const float* gnw = (const float*)d_in[9];
    const float* gnb = (const float*)d_in[10];
    const float* gns = (const float*)d_in[11];
    const float* pw1 = (const float*)d_in[12];
    const float* pb1 = (const float*)d_in[13];
    const float* pw2 = (const float*)d_in[14];
    const float* pb2 = (const float*)d_in[15];
    float* out = (float*)d_out;

    const int EB = (N_EDGES + 255)/256;
    const int NB = (N_NODES + 255)/256;

    k_zero_once<<<NB, 256>>>(out);
    k_hist<<<EB, 256>>>(dst);
    k_count<<<NB, 256>>>(gid);
    k_scan1<<<NBLK, SCAN_B>>>();
    k_scan2<<<1, 128>>>();
    k_scan3<<<NB, 256>>>();
    k_scatter<<<EB, 256>>>(src, dst);

    const int GB = (N_NODES + 63)/64;
    const int AB = (N_NODES*16 + 255)/256;

    for (int l = 0; l < NLAY; l++) {
        int use_x = (l == 0) ? 1 : 0;
        k_agg<<<AB, 256>>>(x, use_x, eps, l);
        k_conv<<<GB, 256>>>(cw1 + l*4096, cb1 + l*64,
                            cw2 + l*4096, cb2 + l*64, gid);
        k_stats<<<(NGRAPH*HID + 255)/256, 256>>>(gns + l*64, gnw + l*64, gnb + l*64);
        k_proj<<<GB, 256>>>(pw1 + l*4096, pb1 + l*64,
                            pw2 + l*2048, pb2 + l*32,
                            gid, out, l);
    }
    k_final<<<(NGRAPH*OUTW + 255)/256, 256>>>(out);
}

// round 6
// speedup vs baseline: 1.3569x; 1.2092x over previous
#include <cuda_runtime.h>
#include <stdint.h>

#define N_NODES 100000
#define N_EDGES 1200000
#define HID     64
#define TGT     32
#define NLAY    3
#define NGRAPH  500
#define OUTW    (NLAY*TGT)   // 96
#define SCAN_B  1024
#define NBLK    ((N_NODES + SCAN_B - 1)/SCAN_B)   // 98

typedef unsigned long long ull;

// ---------------------------------------------------------------- scratch
static __device__ float g_feat[N_NODES*HID];
static __device__ float g_A   [N_NODES*HID];
static __device__ float g_h   [N_NODES*HID];
static __device__ float g_gsum [NGRAPH*HID];
static __device__ float g_gvar [NGRAPH*HID];
static __device__ float g_alpha[NGRAPH*HID];
static __device__ float g_beta [NGRAPH*HID];
static __device__ float g_cnt  [NGRAPH];
static __device__ int   g_deg  [N_NODES];
static __device__ int   g_off  [N_NODES+1];
static __device__ int   g_cursor[N_NODES];
static __device__ int   g_csr  [N_EDGES];
static __device__ int   g_bsum [NBLK];

// ---------------------------------------------------------------- f32x2
__device__ __forceinline__ ull dup2(float x) {
    ull r; asm("mov.b64 %0, {%1, %1};" : "=l"(r) : "f"(x)); return r;
}
__device__ __forceinline__ ull pk2(float x, float y) {
    ull r; asm("mov.b64 %0, {%1, %2};" : "=l"(r) : "f"(x), "f"(y)); return r;
}
__device__ __forceinline__ float2 up2(ull v) {
    float lo, hi; asm("mov.b64 {%0, %1}, %2;" : "=f"(lo), "=f"(hi) : "l"(v));
    return make_float2(lo, hi);
}
__device__ __forceinline__ ull ffma2(ull a, ull b, ull c) {
    ull d; asm("fma.rn.f32x2 %0, %1, %2, %3;" : "=l"(d) : "l"(a), "l"(b), "l"(c));
    return d;
}
__device__ __forceinline__ void redv4(float* p, float4 v) {
    asm volatile("red.global.add.v4.f32 [%0], {%1,%2,%3,%4};"
                 :: "l"(p), "f"(v.x), "f"(v.y), "f"(v.z), "f"(v.w) : "memory");
}

// ---------------------------------------------------------------- setup

__global__ void k_zero_once(float* __restrict__ out) {
    int i = blockIdx.x*blockDim.x + threadIdx.x;
    if (i < N_NODES) g_deg[i] = 0;
    if (i < NGRAPH)  g_cnt[i] = 0.f;
    if (i < NGRAPH*HID) { g_gsum[i] = 0.f; g_gvar[i] = 0.f; }
    if (i < NGRAPH*OUTW) out[i] = 0.f;
}

__global__ void k_hist(const int* __restrict__ dst) {
    int e = blockIdx.x*blockDim.x + threadIdx.x;
    if (e < N_EDGES) atomicAdd(&g_deg[dst[e]], 1);
}

__global__ void k_count(const int* __restrict__ gid) {
    int i = blockIdx.x*blockDim.x + threadIdx.x;
    if (i < N_NODES) atomicAdd(&g_cnt[gid[i]], 1.0f);
}

// ---------------- two-level exclusive scan of degrees

__global__ __launch_bounds__(SCAN_B) void k_scan1() {
    __shared__ int wsum[32];
    int i = blockIdx.x*SCAN_B + threadIdx.x;
    int lane = threadIdx.x & 31, wid = threadIdx.x >> 5;
    int v = (i < N_NODES) ? g_deg[i] : 0;
    int s = v;
    #pragma unroll
    for (int o = 1; o < 32; o <<= 1) {
        int t = __shfl_up_sync(~0u, s, o);
        if (lane >= o) s += t;
    }
    if (lane == 31) wsum[wid] = s;
    __syncthreads();
    if (wid == 0) {
        int ws = wsum[lane];
        #pragma unroll
        for (int o = 1; o < 32; o <<= 1) {
            int t = __shfl_up_sync(~0u, ws, o);
            if (lane >= o) ws += t;
        }
        wsum[lane] = ws;
    }
    __syncthreads();
    int excl = s - v + ((wid > 0) ? wsum[wid-1] : 0);
    if (i < N_NODES) g_off[i] = excl;
    if (threadIdx.x == SCAN_B-1) g_bsum[blockIdx.x] = wsum[31];
}

__global__ __launch_bounds__(128) void k_scan2() {
    __shared__ int buf[128];
    int tid = threadIdx.x;
    int v = (tid < NBLK) ? g_bsum[tid] : 0;
    buf[tid] = v;
    __syncthreads();
    #pragma unroll
    for (int o = 1; o < 128; o <<= 1) {
        int t = (tid >= o) ? buf[tid - o] : 0;
        __syncthreads();
        buf[tid] += t;
        __syncthreads();
    }
    if (tid < NBLK) g_bsum[tid] = buf[tid] - v;
    if (tid == 127) g_off[N_NODES] = buf[127];
}

__global__ void k_scan3() {
    int i = blockIdx.x*blockDim.x + threadIdx.x;
    if (i < N_NODES) {
        int o = g_off[i] + g_bsum[i >> 10];
        g_off[i] = o;
        g_cursor[i] = o;
    }
}

__global__ void k_scatter(const int* __restrict__ src, const int* __restrict__ dst) {
    int e = blockIdx.x*blockDim.x + threadIdx.x;
    if (e < N_EDGES) {
        int p = atomicAdd(&g_cursor[dst[e]], 1);
        g_csr[p] = src[e];
    }
}

// ------------------------------------------------ aggregation (CSR gather)
// 16 lanes per node, each lane owns 4 columns. A = (1+eps)*feat + sum(neigh)
__global__ __launch_bounds__(256) void k_agg(const float* __restrict__ x, int use_x,
                                             const float* __restrict__ eps, int l) {
    unsigned t = blockIdx.x*blockDim.x + threadIdx.x;
    unsigned node = t >> 4;
    if (node >= N_NODES) return;
    int j = (int)(t & 15u) << 2;
    const float* __restrict__ f = use_x ? x : g_feat;
    float sc = 1.0f + eps[l];
    float4 acc = *(const float4*)&f[(size_t)node*HID + j];
    acc.x *= sc; acc.y *= sc; acc.z *= sc; acc.w *= sc;
    int b = g_off[node], e = g_off[node+1];
    for (; b + 4 <= e; b += 4) {
        int s0 = g_csr[b], s1 = g_csr[b+1], s2 = g_csr[b+2], s3 = g_csr[b+3];
        float4 v0 = *(const float4*)&f[(size_t)s0*HID + j];
        float4 v1 = *(const float4*)&f[(size_t)s1*HID + j];
        float4 v2 = *(const float4*)&f[(size_t)s2*HID + j];
        float4 v3 = *(const float4*)&f[(size_t)s3*HID + j];
        acc.x += (v0.x + v1.x) + (v2.x + v3.x);
        acc.y += (v0.y + v1.y) + (v2.y + v3.y);
        acc.z += (v0.z + v1.z) + (v2.z + v3.z);
        acc.w += (v0.w + v1.w) + (v2.w + v3.w);
    }
    for (; b < e; b++) {
        int s = g_csr[b];
        float4 v = *(const float4*)&f[(size_t)s*HID + j];
        acc.x += v.x; acc.y += v.y; acc.z += v.z; acc.w += v.w;
    }
    *(float4*)&g_A[(size_t)node*HID + j] = acc;
}

// ============================================================ fused kernel 1
// MLP (2 GEMMs), thread tile = 4 cols x 4 rows, + GN stats epilogue
__global__ __launch_bounds__(256) void k_conv(
    const float* __restrict__ w1, const float* __restrict__ b1,
    const float* __restrict__ w2, const float* __restrict__ b2,
    const int*   __restrict__ gid)
{
    __shared__ float W1s[4096];      // row-major [k][c]
    __shared__ float W2s[4096];
    __shared__ float As [64*68];
    __shared__ float b1s[64], b2s[64];
    __shared__ int   gids[64];

    const int tid  = threadIdx.x;
    const int row0 = blockIdx.x * 64;

    for (int i = tid; i < 4096; i += 256) { W1s[i] = w1[i]; W2s[i] = w2[i]; }
    if (tid < 64) {
        b1s[tid] = b1[tid]; b2s[tid] = b2[tid];
        int r = row0 + tid;
        gids[tid] = (r < N_NODES) ? gid[r] : 0;
    }
    #pragma unroll
    for (int it = 0; it < 4; it++) {
        int i = it*256 + tid;
        int r = i >> 4, kk = (i & 15) << 2;
        int row = row0 + r;
        float4 v = make_float4(0.f,0.f,0.f,0.f);
        if (row < N_NODES) v = *(const float4*)&g_A[(size_t)row*64 + kk];
        *(float4*)&As[r*68 + kk] = v;
    }
    __syncthreads();

    const int c0 = (tid & 15) << 2;    // 4 output columns c0..c0+3
    const int rg = tid >> 4;           // 4 rows rg*4 .. rg*4+3
    const float* arow = &As[rg*4*68];

    ull acc0[4], acc1[4];
    // ---- GEMM1
    {
        ull bi0 = pk2(b1s[c0],   b1s[c0+1]);
        ull bi1 = pk2(b1s[c0+2], b1s[c0+3]);
        #pragma unroll
        for (int r = 0; r < 4; r++) { acc0[r] = bi0; acc1[r] = bi1; }
    }
    #pragma unroll 4
    for (int kc = 0; kc < 64; kc += 4) {
        float4 a0 = *(const float4*)&arow[0*68 + kc];
        float4 a1 = *(const float4*)&arow[1*68 + kc];
        float4 a2 = *(const float4*)&arow[2*68 + kc];
        float4 a3 = *(const float4*)&arow[3*68 + kc];
        #pragma unroll
        for (int kk = 0; kk < 4; kk++) {
            float4 w = *(const float4*)&W1s[(kc+kk)*64 + c0];
            ull wp0 = pk2(w.x, w.y), wp1 = pk2(w.z, w.w);
            float e0 = (kk==0)?a0.x:(kk==1)?a0.y:(kk==2)?a0.z:a0.w;
            float e1 = (kk==0)?a1.x:(kk==1)?a1.y:(kk==2)?a1.z:a1.w;
            float e2 = (kk==0)?a2.x:(kk==1)?a2.y:(kk==2)?a2.z:a2.w;
            float e3 = (kk==0)?a3.x:(kk==1)?a3.y:(kk==2)?a3.z:a3.w;
            ull d0 = dup2(e0), d1 = dup2(e1), d2 = dup2(e2), d3 = dup2(e3);
            acc0[0] = ffma2(d0, wp0, acc0[0]); acc1[0] = ffma2(d0, wp1, acc1[0]);
            acc0[1] = ffma2(d1, wp0, acc0[1]); acc1[1] = ffma2(d1, wp1, acc1[1]);
            acc0[2] = ffma2(d2, wp0, acc0[2]); acc1[2] = ffma2(d2, wp1, acc1[2]);
            acc0[3] = ffma2(d3, wp0, acc0[3]); acc1[3] = ffma2(d3, wp1, acc1[3]);
        }
    }
    __syncthreads();
    #pragma unroll
    for (int r = 0; r < 4; r++) {
        float2 p0 = up2(acc0[r]), p1 = up2(acc1[r]);
        *(float4*)&As[(rg*4+r)*68 + c0] = make_float4(
            fmaxf(p0.x,0.f), fmaxf(p0.y,0.f), fmaxf(p1.x,0.f), fmaxf(p1.y,0.f));
    }
    __syncthreads();

    // ---- GEMM2
    {
        ull bi0 = pk2(b2s[c0],   b2s[c0+1]);
        ull bi1 = pk2(b2s[c0+2], b2s[c0+3]);
        #pragma unroll
        for (int r = 0; r < 4; r++) { acc0[r] = bi0; acc1[r] = bi1; }
    }
    #pragma unroll 4
    for (int kc = 0; kc < 64; kc += 4) {
        float4 a0 = *(const float4*)&arow[0*68 + kc];
        float4 a1 = *(const float4*)&arow[1*68 + kc];
        float4 a2 = *(const float4*)&arow[2*68 + kc];
        float4 a3 = *(const float4*)&arow[3*68 + kc];
        #pragma unroll
        for (int kk = 0; kk < 4; kk++) {
            float4 w = *(const float4*)&W2s[(kc+kk)*64 + c0];
            ull wp0 = pk2(w.x, w.y), wp1 = pk2(w.z, w.w);
            float e0 = (kk==0)?a0.x:(kk==1)?a0.y:(kk==2)?a0.z:a0.w;
            float e1 = (kk==0)?a1.x:(kk==1)?a1.y:(kk==2)?a1.z:a1.w;
            float e2 = (kk==0)?a2.x:(kk==1)?a2.y:(kk==2)?a2.z:a2.w;
            float e3 = (kk==0)?a3.x:(kk==1)?a3.y:(kk==2)?a3.z:a3.w;
            ull d0 = dup2(e0), d1 = dup2(e1), d2 = dup2(e2), d3 = dup2(e3);
            acc0[0] = ffma2(d0, wp0, acc0[0]); acc1[0] = ffma2(d0, wp1, acc1[0]);
            acc0[1] = ffma2(d1, wp0, acc0[1]); acc1[1] = ffma2(d1, wp1, acc1[1]);
            acc0[2] = ffma2(d2, wp0, acc0[2]); acc1[2] = ffma2(d2, wp1, acc1[2]);
            acc0[3] = ffma2(d3, wp0, acc0[3]); acc1[3] = ffma2(d3, wp1, acc1[3]);
        }
    }

    // ---- epilogue: write h, per-graph sum(h) and sum(h^2), vector red
    float4 s = make_float4(0.f,0.f,0.f,0.f);
    float4 q = make_float4(0.f,0.f,0.f,0.f);
    int cur = gids[rg*4];
    #pragma unroll
    for (int r = 0; r < 4; r++) {
        int row = row0 + rg*4 + r;
        if (row < N_NODES) {
            float2 p0 = up2(acc0[r]), p1 = up2(acc1[r]);
            float4 h = make_float4(p0.x, p0.y, p1.x, p1.y);
            *(float4*)&g_h[(size_t)row*64 + c0] = h;
            int g = gids[rg*4 + r];
            if (g != cur) {
                redv4(&g_gsum[cur*64 + c0], s);
                redv4(&g_gvar[cur*64 + c0], q);
                s = make_float4(0.f,0.f,0.f,0.f);
                q = make_float4(0.f,0.f,0.f,0.f);
                cur = g;
            }
            s.x += h.x; s.y += h.y; s.z += h.z; s.w += h.w;
            q.x += h.x*h.x; q.y += h.y*h.y; q.z += h.z*h.z; q.w += h.w*h.w;
        }
    }
    redv4(&g_gsum[cur*64 + c0], s);
    redv4(&g_gvar[cur*64 + c0], q);
}

// ------------------------------------------------ per-(graph,ch) norm coeffs
__global__ void k_stats(const float* __restrict__ gns,
                        const float* __restrict__ gnw,
                        const float* __restrict__ gnb) {
    int i = blockIdx.x*blockDim.x + threadIdx.x;
    if (i >= NGRAPH*HID) return;
    int c = i & 63, g = i >> 6;
    float n  = fmaxf(g_cnt[g], 1.f);
    float m  = g_gsum[i] / n;
    float e2 = g_gvar[i] / n;
    float s  = gns[c];
    float var = e2 - m*m*s*(2.f - s);
    float sd  = sqrtf(fmaxf(var, 0.f) + 1e-8f);
    float al  = gnw[c] / sd;
    g_alpha[i] = al;
    g_beta[i]  = gnb[c] - al*m*s;
    g_gsum[i] = 0.f;
    g_gvar[i] = 0.f;
}

// ============================================================ fused kernel 2
// GraphNorm affine+relu -> proj MLP (GEMM1 4x4 tile, GEMM2 as R3) -> pooling
__global__ __launch_bounds__(256) void k_proj(
    const float* __restrict__ pw1, const float* __restrict__ pb1,
    const float* __restrict__ pw2, const float* __restrict__ pb2,
    const int*   __restrict__ gid, float* __restrict__ out, int l)
{
    __shared__ float W1s[4096];      // row-major [k][c]
    __shared__ float W2s[2048];      // row-major [k][c], 32 cols
    __shared__ float As [64*68];
    __shared__ float b1s[64], b2s[32];
    __shared__ int   gids[64];

    const int tid  = threadIdx.x;
    const int row0 = blockIdx.x * 64;

    for (int i = tid; i < 4096; i += 256) W1s[i] = pw1[i];
    for (int i = tid; i < 2048; i += 256) W2s[i] = pw2[i];
    if (tid < 64) {
        b1s[tid] = pb1[tid];
        int r = row0 + tid;
        gids[tid] = (r < N_NODES) ? gid[r] : 0;
    }
    if (tid < 32) b2s[tid] = pb2[tid];
    __syncthreads();

    // ---- GraphNorm affine + relu -> As (+ g_feat for next layer)
    #pragma unroll
    for (int it = 0; it < 4; it++) {
        int i = it*256 + tid;
        int r = i >> 4, kk = (i & 15) << 2;
        int row = row0 + r;
        float4 v = make_float4(0.f,0.f,0.f,0.f);
        if (row < N_NODES) {
            int g = gids[r];
            float4 h  = *(const float4*)&g_h[(size_t)row*64 + kk];
            float4 al = *(const float4*)&g_alpha[g*64 + kk];
            float4 be = *(const float4*)&g_beta[g*64 + kk];
            v.x = fmaxf(fmaf(al.x, h.x, be.x), 0.f);
            v.y = fmaxf(fmaf(al.y, h.y, be.y), 0.f);
            v.z = fmaxf(fmaf(al.z, h.z, be.z), 0.f);
            v.w = fmaxf(fmaf(al.w, h.w, be.w), 0.f);
            *(float4*)&g_feat[(size_t)row*64 + kk] = v;
        }
        *(float4*)&As[r*68 + kk] = v;
    }
    __syncthreads();

    // ---- GEMM1: 64x64, 4 cols x 4 rows per thread
    {
        const int c0 = (tid & 15) << 2;
        const int rg = tid >> 4;
        const float* arow = &As[rg*4*68];
        ull acc0[4], acc1[4];
        ull bi0 = pk2(b1s[c0],   b1s[c0+1]);
        ull bi1 = pk2(b1s[c0+2], b1s[c0+3]);
        #pragma unroll
        for (int r = 0; r < 4; r++) { acc0[r] = bi0; acc1[r] = bi1; }
        #pragma unroll 4
        for (int kc = 0; kc < 64; kc += 4) {
            float4 a0 = *(const float4*)&arow[0*68 + kc];
            float4 a1 = *(const float4*)&arow[1*68 + kc];
            float4 a2 = *(const float4*)&arow[2*68 + kc];
            float4 a3 = *(const float4*)&arow[3*68 + kc];
            #pragma unroll
            for (int kk = 0; kk < 4; kk++) {
                float4 w = *(const float4*)&W1s[(kc+kk)*64 + c0];
                ull wp0 = pk2(w.x, w.y), wp1 = pk2(w.z, w.w);
                float e0 = (kk==0)?a0.x:(kk==1)?a0.y:(kk==2)?a0.z:a0.w;
                float e1 = (kk==0)?a1.x:(kk==1)?a1.y:(kk==2)?a1.z:a1.w;
                float e2 = (kk==0)?a2.x:(kk==1)?a2.y:(kk==2)?a2.z:a2.w;
                float e3 = (kk==0)?a3.x:(kk==1)?a3.y:(kk==2)?a3.z:a3.w;
                ull d0 = dup2(e0), d1 = dup2(e1), d2 = dup2(e2), d3 = dup2(e3);
                acc0[0] = ffma2(d0, wp0, acc0[0]); acc1[0] = ffma2(d0, wp1, acc1[0]);
                acc0[1] = ffma2(d1, wp0, acc0[1]); acc1[1] = ffma2(d1, wp1, acc1[1]);
                acc0[2] = ffma2(d2, wp0, acc0[2]); acc1[2] = ffma2(d2, wp1, acc1[2]);
                acc0[3] = ffma2(d3, wp0, acc0[3]); acc1[3] = ffma2(d3, wp1, acc1[3]);
            }
        }
        __syncthreads();
        #pragma unroll
        for (int r = 0; r < 4; r++) {
            float2 p0 = up2(acc0[r]), p1 = up2(acc1[r]);
            *(float4*)&As[(rg*4+r)*68 + c0] = make_float4(
                fmaxf(p0.x,0.f), fmaxf(p0.y,0.f), fmaxf(p1.x,0.f), fmaxf(p1.y,0.f));
        }
    }
    __syncthreads();

    // ---- GEMM2: 64 -> 32 (R3 layout: 1 col-pair... col c, 8 rows, dup2 form)
    {
        const int c  = tid & 31;
        const int rg = tid >> 5;
        const float* arow = &As[rg*8*68];
        ull acc[8];
        ull binit = pk2(b2s[c], 0.f);
        #pragma unroll
        for (int rr = 0; rr < 8; rr++) acc[rr] = binit;
        #pragma unroll 4
        for (int kc = 0; kc < 64; kc += 4) {
            float2 w01 = make_float2(W2s[(kc+0)*32 + c], W2s[(kc+1)*32 + c]);
            float2 w23 = make_float2(W2s[(kc+2)*32 + c], W2s[(kc+3)*32 + c]);
            ull wp0 = pk2(w01.x, w01.y), wp1 = pk2(w23.x, w23.y);
            #pragma unroll
            for (int rr = 0; rr < 8; rr++) {
                float4 a = *(const float4*)&arow[rr*68 + kc];
                acc[rr] = ffma2(pk2(a.x, a.y), wp0, acc[rr]);
                acc[rr] = ffma2(pk2(a.z, a.w), wp1, acc[rr]);
            }
        }

        // pooling epilogue
        float s = 0.f;
        int cur = gids[rg*8];
        #pragma unroll
        for (int rr = 0; rr < 8; rr++) {
            int row = row0 + rg*8 + rr;
            if (row < N_NODES) {
                float2 p = up2(acc[rr]);
                float z = p.x + p.y;
                int g = gids[rg*8 + rr];
                if (g != cur) {
                    atomicAdd(&out[cur*OUTW + l*TGT + c], s);
                    s = 0.f; cur = g;
                }
                s += z;
            }
        }
        atomicAdd(&out[cur*OUTW + l*TGT + c], s);
    }
}

__global__ void k_final(float* __restrict__ out) {
    int i = blockIdx.x*blockDim.x + threadIdx.x;
    if (i < NGRAPH*OUTW) out[i] /= fmaxf(g_cnt[i / OUTW], 1.f);
}

// ---------------------------------------------------------------- launcher

extern "C" void kernel_launch(void* const* d_in, const int* in_sizes, int n_in,
                              void* d_out, int out_size) {
    const float* x   = (const float*)d_in[0];
    const int*   src = (const int*)  d_in[1];
    const int*   dst = (const int*)  d_in[2];
    const int*   gid = (const int*)  d_in[3];
    const float* eps = (const float*)d_in[4];
    const float* cw1 = (const float*)d_in[5];
    const float* cb1 = (const float*)d_in[6];
    const float* cw2 = (const float*)d_in[7];
    const float* cb2 = (const float*)d_in[8];
    const float* gnw = (const float*)d_in[9];
    const float* gnb = (const float*)d_in[10];
    const float* gns = (const float*)d_in[11];
    const float* pw1 = (const float*)d_in[12];
    const float* pb1 = (const float*)d_in[13];
    const float* pw2 = (const float*)d_in[14];
    const float* pb2 = (const float*)d_in[15];
    float* out = (float*)d_out;

    const int EB = (N_EDGES + 255)/256;
    const int NB = (N_NODES + 255)/256;

    k_zero_once<<<NB, 256>>>(out);
    k_hist<<<EB, 256>>>(dst);
    k_count<<<NB, 256>>>(gid);
    k_scan1<<<NBLK, SCAN_B>>>();
    k_scan2<<<1, 128>>>();
    k_scan3<<<NB, 256>>>();
    k_scatter<<<EB, 256>>>(src, dst);

    const int GB = (N_NODES + 63)/64;
    const int AB = (N_NODES*16 + 255)/256;

    for (int l = 0; l < NLAY; l++) {
        int use_x = (l == 0) ? 1 : 0;
        k_agg<<<AB, 256>>>(x, use_x, eps, l);
        k_conv<<<GB, 256>>>(cw1 + l*4096, cb1 + l*64,
                            cw2 + l*4096, cb2 + l*64, gid);
        k_stats<<<(NGRAPH*HID + 255)/256, 256>>>(gns + l*64, gnw + l*64, gnb + l*64);
        k_proj<<<GB, 256>>>(pw1 + l*4096, pb1 + l*64,
                            pw2 + l*2048, pb2 + l*32,
                            gid, out, l);
    }
    k_final<<<(NGRAPH*OUTW + 255)/256, 256>>>(out);
}